// round 15
// baseline (speedup 1.0000x reference)
#include <cuda_runtime.h>
#include <cuda_bf16.h>

// Problem constants
#define Hc 200          // H
#define Wc 196          // W
#define NPIX (Hc * Wc)  // 39200 pixels per camera
#define NCH 256
#define NCHUNK 4
#define CHCH (NCH / NCHUNK)  // 64 channels per chunk
#define NCAM 6
#define SSZ 400
#define NCELL (SSZ * SSZ)    // 160000

#define XT 154                       // pixel tiles of 256
#define NTILES (XT * NCAM * NCHUNK)  // 3696
#define GRIDB 1184                   // 148 SMs x 8 resident blocks: ALL co-resident

// Scratch (allocation-free rule). Zero at module load; the kernel itself
// restores everything to zero before exit, so state is zero at every
// kernel_launch entry (correctness run and every graph replay).
__device__ float g_sum[NCELL];
__device__ float g_cnt[NCELL];
__device__ unsigned int g_ticket;  // dynamic tile ticket
__device__ unsigned int g_done;    // blocks finished scatter phase
__device__ unsigned int g_done2;   // blocks finished finalize (reset handshake)

// Single persistent kernel:
//   phase 1: dynamic-ticket loop over 3696 (pixtile, cam, chunk) tiles.
//            Scalar LDG.32 streaming (1 x 128B line per warp load), partial
//            dots atomically scattered (linear in channels); chunk 0 adds
//            counts. Perfect load balance via tickets.
//   phase 2: software grid barrier (deadlock-free: occupancy math guarantees
//            all 1184 blocks resident), then inline finalize + scratch
//            re-zero + counter reset by the last block.
// Mask read as 32-bit word: correct for int32 AND float32 bool storage
// (true nonzero in both); u8 ruled out empirically in R1. Meshgrid computed
// analytically (exact np.linspace replication in double).
__global__ __launch_bounds__(256, 8) void bev_fused_kernel(
    const float* __restrict__ feats,   // [NCAM, NCH, Wc, Hc]
    const float* __restrict__ mats,    // [NCAM, 4, 4]
    const int*   __restrict__ mask,    // [NPIX], n = h*W + w
    const float* __restrict__ w_cls,   // [NCH]
    const float* __restrict__ b_cls,   // [1]
    float*       __restrict__ out)     // [NCELL]
{
    __shared__ float sw[NCH];
    __shared__ float sm[NCAM * 16];
    __shared__ unsigned int s_t;

    const int tid = threadIdx.x;

    sw[tid] = w_cls[tid];
    if (tid < NCAM * 16) sm[tid] = mats[tid];
    // (first __syncthreads below covers these shared writes)

    // ---------- phase 1: scatter ----------
    for (;;) {
        __syncthreads();                       // protects s_t reuse + initial smem
        if (tid == 0) s_t = atomicAdd(&g_ticket, 1u);
        __syncthreads();
        const unsigned int t = s_t;
        if (t >= NTILES) break;

        const int xt    = (int)t % XT;
        const int rc    = (int)t / XT;
        const int cam   = rc % NCAM;
        const int chunk = rc / NCAM;

        const int pix = xt * 256 + tid;
        if (pix >= NPIX) continue;

        const float* p = feats + (size_t)cam * NCH * NPIX
                       + (size_t)chunk * CHCH * NPIX + pix;
        const float* w = sw + chunk * CHCH;

        float a0 = 0.f, a1 = 0.f, a2 = 0.f, a3 = 0.f;
#pragma unroll 8
        for (int ch = 0; ch < CHCH; ch += 4) {
            a0 = fmaf(p[(ch + 0) * NPIX], w[ch + 0], a0);
            a1 = fmaf(p[(ch + 1) * NPIX], w[ch + 1], a1);
            a2 = fmaf(p[(ch + 2) * NPIX], w[ch + 2], a2);
            a3 = fmaf(p[(ch + 3) * NPIX], w[ch + 3], a3);
        }
        const float dot = (a0 + a1) + (a2 + a3);

        // pix = w*H + h ; logical flat index n = h*W + w
        const int wq = pix / Hc;
        const int h  = pix - wq * Hc;
        const int n  = h * Wc + wq;

        if (mask[n] != 0) {
            // xs = linspace(-25,25,200)[h], ys = linspace(1,50,196)[w]
            const float gx = (float)(-25.0 + (double)h  * (50.0 / 199.0));
            const float gy = (float)(  1.0 + (double)wq * (49.0 / 195.0));
            const float* M = sm + cam * 16;
            const float x = M[0] * gx + M[1] * gy + M[3];
            const float y = M[4] * gx + M[5] * gy + M[7];
            // (coord + 100) / 0.5 == (coord + 100) * 2 exactly; jnp.round == rintf
            const float fx = rintf((x + 100.0f) * 2.0f);
            const float fy = rintf((y + 100.0f) * 2.0f);
            if (fx >= 0.0f && fx < (float)SSZ && fy >= 0.0f && fy < (float)SSZ) {
                const int cell = (int)fx * SSZ + (int)fy;
                atomicAdd(&g_sum[cell], dot);
                if (chunk == 0) atomicAdd(&g_cnt[cell], 1.0f);
            }
        }
    }

    // ---------- grid barrier (all GRIDB blocks are resident) ----------
    if (tid == 0) {
        __threadfence();
        atomicAdd(&g_done, 1u);
        while (atomicAdd(&g_done, 0u) < GRIDB) __nanosleep(64);
    }
    __syncthreads();

    // ---------- phase 2: finalize + re-zero ----------
    {
        const int i4 = blockIdx.x * 256 + tid;
        if (i4 < NCELL / 4) {
            float4* s4 = (float4*)g_sum + i4;
            float4* c4 = (float4*)g_cnt + i4;
            // atomics wrote L2-resident data; bypass L1 on read
            float4 s, c;
            s.x = __ldcg(&((const float*)s4)[0]);
            s.y = __ldcg(&((const float*)s4)[1]);
            s.z = __ldcg(&((const float*)s4)[2]);
            s.w = __ldcg(&((const float*)s4)[3]);
            c.x = __ldcg(&((const float*)c4)[0]);
            c.y = __ldcg(&((const float*)c4)[1]);
            c.z = __ldcg(&((const float*)c4)[2]);
            c.w = __ldcg(&((const float*)c4)[3]);
            const float b = b_cls[0];
            float4 o;
            // where(cnt>=1, sum/max(cnt,1), sum) == sum/max(cnt,1): sum==0 if cnt==0
            o.x = s.x / fmaxf(c.x, 1.0f) + b;
            o.y = s.y / fmaxf(c.y, 1.0f) + b;
            o.z = s.z / fmaxf(c.z, 1.0f) + b;
            o.w = s.w / fmaxf(c.w, 1.0f) + b;
            ((float4*)out)[i4] = o;
            float4 z = make_float4(0.f, 0.f, 0.f, 0.f);
            *s4 = z;
            *c4 = z;
        }
    }

    // ---------- reset handshake: last block restores counters to zero ----------
    __threadfence();
    __syncthreads();
    if (tid == 0) {
        unsigned int d = atomicAdd(&g_done2, 1u);
        if (d == GRIDB - 1) {
            g_ticket = 0u;
            g_done   = 0u;
            g_done2  = 0u;
            __threadfence();
        }
    }
}

extern "C" void kernel_launch(void* const* d_in, const int* in_sizes, int n_in,
                              void* d_out, int out_size) {
    // Resolve inputs by element count (all distinct) — robust to metadata order.
    const float* feats = 0; const float* mats = 0;
    const int*   mask  = 0; const float* w_cls = 0; const float* b_cls = 0;
    for (int i = 0; i < n_in; i++) {
        switch (in_sizes[i]) {
            case 60211200: feats = (const float*)d_in[i]; break;
            case 96:       mats  = (const float*)d_in[i]; break;
            case 39200:    mask  = (const int*)d_in[i];   break;
            case 256:      w_cls = (const float*)d_in[i]; break;
            case 1:        b_cls = (const float*)d_in[i]; break;
            default: break;  // 156800 (lc) unused: meshgrid computed analytically
        }
    }
    float* out = (float*)d_out;

    bev_fused_kernel<<<GRIDB, 256>>>(feats, mats, mask, w_cls, b_cls, out);
}

// round 16
// speedup vs baseline: 1.1284x; 1.1284x over previous
#include <cuda_runtime.h>
#include <cuda_bf16.h>

// Problem constants
#define Hc 200          // H
#define Wc 196          // W
#define NPIX (Hc * Wc)  // 39200 pixels per camera
#define NCH 256
#define NCHUNK 4
#define CHCH (NCH / NCHUNK)  // 64 channels per chunk
#define NCAM 6
#define SSZ 400
#define NCELL (SSZ * SSZ)    // 160000

// Scratch (allocation-free rule). Zero at module load; finalize re-zeros after
// reading, so the grids are zero at every kernel_launch entry (correctness run
// and every graph replay).
__device__ float g_sum[NCELL];
__device__ float g_cnt[NCELL];

// Main kernel (best measured config, R13): one thread per (cam, pixel,
// channel-chunk). Scalar LDG.32 streaming (1 x 128B line per warp load).
// NCHUNK=4 -> 3696 blocks, ~25 tiles/SM via CWD backfill (fine-grained
// amortization of tile quantization — NOT a persistent grid+barrier, which
// R14 showed converts 4-vs-3 tile quantization into a 28% tail).
// regs forced <=32 so 8 blocks = 64 warps/SM resident.
// Partial dots accumulate atomically (scatter-add is linear in channels);
// chunk 0 adds the count. Mask read as 32-bit word: correct for int32 AND
// float32 bool storage; u8 ruled out empirically in R1. Meshgrid computed
// analytically (exact np.linspace replication in double).
__global__ __launch_bounds__(256, 8) void bev_dot_scatter_kernel(
    const float* __restrict__ feats,   // [NCAM, NCH, Wc, Hc]
    const float* __restrict__ mats,    // [NCAM, 4, 4]
    const int*   __restrict__ mask,    // [NPIX], n = h*W + w
    const float* __restrict__ w_cls)   // [NCH]
{
    __shared__ float sw[CHCH];
    __shared__ float sm[8];  // rows 0,1 of this cam's 4x4

    const int tid   = threadIdx.x;
    const int cam   = blockIdx.y;
    const int chunk = blockIdx.z;

    if (tid < CHCH) sw[tid] = w_cls[chunk * CHCH + tid];
    if (tid < 8)    sm[tid] = mats[cam * 16 + tid];
    __syncthreads();

    const int pix = blockIdx.x * 256 + tid;
    if (pix >= NPIX) return;

    const float* p = feats + (size_t)cam * NCH * NPIX
                   + (size_t)chunk * CHCH * NPIX + pix;

    float a0 = 0.f, a1 = 0.f, a2 = 0.f, a3 = 0.f;
#pragma unroll 8
    for (int ch = 0; ch < CHCH; ch += 4) {
        a0 = fmaf(p[(ch + 0) * NPIX], sw[ch + 0], a0);
        a1 = fmaf(p[(ch + 1) * NPIX], sw[ch + 1], a1);
        a2 = fmaf(p[(ch + 2) * NPIX], sw[ch + 2], a2);
        a3 = fmaf(p[(ch + 3) * NPIX], sw[ch + 3], a3);
    }
    const float dot = (a0 + a1) + (a2 + a3);

    // pix = w*H + h ; logical flat index n = h*W + w
    const int wq = pix / Hc;
    const int h  = pix - wq * Hc;
    const int n  = h * Wc + wq;

    if (mask[n] != 0) {
        // xs = linspace(-25,25,200)[h], ys = linspace(1,50,196)[w]
        const float gx = (float)(-25.0 + (double)h  * (50.0 / 199.0));
        const float gy = (float)(  1.0 + (double)wq * (49.0 / 195.0));
        const float x = sm[0] * gx + sm[1] * gy + sm[3];
        const float y = sm[4] * gx + sm[5] * gy + sm[7];
        // (coord + 100) / 0.5 == (coord + 100) * 2 exactly; jnp.round == rintf
        const float fx = rintf((x + 100.0f) * 2.0f);
        const float fy = rintf((y + 100.0f) * 2.0f);
        if (fx >= 0.0f && fx < (float)SSZ && fy >= 0.0f && fy < (float)SSZ) {
            const int cell = (int)fx * SSZ + (int)fy;
            atomicAdd(&g_sum[cell], dot);
            if (chunk == 0) atomicAdd(&g_cnt[cell], 1.0f);
        }
    }
}

// Finalize AND restore scratch to zero for the next run (graph replay invariant).
__global__ __launch_bounds__(256) void finalize_kernel(float* __restrict__ out,
                                                       const float* __restrict__ b_cls) {
    int i4 = blockIdx.x * 256 + threadIdx.x;
    if (i4 >= NCELL / 4) return;
    float* s4 = g_sum + i4 * 4;
    float* c4 = g_cnt + i4 * 4;
    // atomics left this data L2-resident; bypass the guaranteed-miss L1 lookup
    float4 s, c;
    s.x = __ldcg(s4 + 0); s.y = __ldcg(s4 + 1); s.z = __ldcg(s4 + 2); s.w = __ldcg(s4 + 3);
    c.x = __ldcg(c4 + 0); c.y = __ldcg(c4 + 1); c.z = __ldcg(c4 + 2); c.w = __ldcg(c4 + 3);
    const float b = b_cls[0];
    float4 o;
    // where(cnt>=1, sum/max(cnt,1), sum) == sum/max(cnt,1): sum==0 when cnt==0
    o.x = s.x / fmaxf(c.x, 1.0f) + b;
    o.y = s.y / fmaxf(c.y, 1.0f) + b;
    o.z = s.z / fmaxf(c.z, 1.0f) + b;
    o.w = s.w / fmaxf(c.w, 1.0f) + b;
    ((float4*)out)[i4] = o;
    float4 z = make_float4(0.f, 0.f, 0.f, 0.f);
    *(float4*)s4 = z;
    *(float4*)c4 = z;
}

extern "C" void kernel_launch(void* const* d_in, const int* in_sizes, int n_in,
                              void* d_out, int out_size) {
    // Resolve inputs by element count (all distinct) — robust to metadata order.
    const float* feats = 0; const float* mats = 0;
    const int*   mask  = 0; const float* w_cls = 0; const float* b_cls = 0;
    for (int i = 0; i < n_in; i++) {
        switch (in_sizes[i]) {
            case 60211200: feats = (const float*)d_in[i]; break;
            case 96:       mats  = (const float*)d_in[i]; break;
            case 39200:    mask  = (const int*)d_in[i];   break;
            case 256:      w_cls = (const float*)d_in[i]; break;
            case 1:        b_cls = (const float*)d_in[i]; break;
            default: break;  // 156800 (lc) unused: meshgrid computed analytically
        }
    }
    float* out = (float*)d_out;

    dim3 grid((NPIX + 255) / 256, NCAM, NCHUNK);  // 154 x 6 x 4 = 3696 blocks
    bev_dot_scatter_kernel<<<grid, 256>>>(feats, mats, mask, w_cls);

    finalize_kernel<<<(NCELL / 4 + 255) / 256, 256>>>(out, b_cls);
}